// round 1
// baseline (speedup 1.0000x reference)
#include <cuda_runtime.h>
#include <math.h>

#define B_ 8
#define N_ 1024
#define D_ 512
#define H_ 8
#define HD_ 64
#define M_ (B_ * N_)   // 8192 rows

// Scratch (device globals: allocation-free per harness rules)
__device__ float g_q[M_ * D_];
__device__ float g_k[M_ * D_];
__device__ float g_v[M_ * D_];
__device__ float g_ao[M_ * D_];
__device__ float g_pr[M_ * D_];

// ---------------------------------------------------------------------------
// SGEMM: C[M,Nc] = A[M,K] @ W[Nc,K]^T   (both operands K-contiguous, row-major)
// 64x64 block tile, BK=16, 256 threads, 4x4 per-thread microtile.
// ---------------------------------------------------------------------------
__global__ __launch_bounds__(256) void sgemm_nt_kernel(
    const float* __restrict__ A, const float* __restrict__ W,
    float* __restrict__ C, int M, int Nc, int K)
{
    const int BM = 64, BN = 64, BK = 16;
    __shared__ float As[BK][BM];
    __shared__ float Ws[BK][BN];

    int t  = threadIdx.x;
    int tx = t & 15;        // 0..15 -> col group
    int ty = t >> 4;        // 0..15 -> row group
    int m0 = blockIdx.y * BM;
    int n0 = blockIdx.x * BN;

    // loader mapping: 256 threads load 64 rows x 16 k as float4
    int lr = t >> 2;          // 0..63
    int lc = (t & 3) * 4;     // 0,4,8,12

    float acc[4][4];
#pragma unroll
    for (int i = 0; i < 4; i++)
#pragma unroll
        for (int j = 0; j < 4; j++) acc[i][j] = 0.0f;

    for (int k0 = 0; k0 < K; k0 += BK) {
        float4 a = *reinterpret_cast<const float4*>(&A[(size_t)(m0 + lr) * K + k0 + lc]);
        As[lc + 0][lr] = a.x; As[lc + 1][lr] = a.y;
        As[lc + 2][lr] = a.z; As[lc + 3][lr] = a.w;
        float4 w = *reinterpret_cast<const float4*>(&W[(size_t)(n0 + lr) * K + k0 + lc]);
        Ws[lc + 0][lr] = w.x; Ws[lc + 1][lr] = w.y;
        Ws[lc + 2][lr] = w.z; Ws[lc + 3][lr] = w.w;
        __syncthreads();

#pragma unroll
        for (int kk = 0; kk < BK; kk++) {
            float av[4], wv[4];
            *reinterpret_cast<float4*>(av) = *reinterpret_cast<float4*>(&As[kk][ty * 4]);
            *reinterpret_cast<float4*>(wv) = *reinterpret_cast<float4*>(&Ws[kk][tx * 4]);
#pragma unroll
            for (int i = 0; i < 4; i++)
#pragma unroll
                for (int j = 0; j < 4; j++)
                    acc[i][j] = fmaf(av[i], wv[j], acc[i][j]);
        }
        __syncthreads();
    }

#pragma unroll
    for (int i = 0; i < 4; i++) {
        float4 r = make_float4(acc[i][0], acc[i][1], acc[i][2], acc[i][3]);
        *reinterpret_cast<float4*>(&C[(size_t)(m0 + ty * 4 + i) * Nc + n0 + tx * 4]) = r;
    }
}

// ---------------------------------------------------------------------------
// Attention: one CTA (128 threads) per (query row n, head h, batch b).
// scores[1024] in smem; masked softmax; weighted sum over V.
// ---------------------------------------------------------------------------
__global__ __launch_bounds__(128) void attn_kernel(
    const float* __restrict__ q, const float* __restrict__ k,
    const float* __restrict__ v, const int* __restrict__ adj,
    float* __restrict__ out)
{
    int n = blockIdx.x, h = blockIdx.y, b = blockIdx.z;
    int tid = threadIdx.x;

    __shared__ float sq[HD_];
    __shared__ float sc[N_];
    __shared__ float red[4];
    __shared__ float sacc[HD_];

    if (tid < HD_)
        sq[tid] = q[((size_t)(b * N_ + n)) * D_ + h * HD_ + tid];
    __syncthreads();

    const int*   arow = adj + ((size_t)b * N_ + n) * N_;
    const float* kb   = k + (size_t)b * N_ * D_ + h * HD_;

    float lmax = -1e30f;
    for (int j = tid; j < N_; j += 128) {
        float s;
        if (arow[j] <= 0) {
            s = -10000.0f;
        } else {
            const float* kr = kb + (size_t)j * D_;
            float d0 = 0.f, d1 = 0.f, d2 = 0.f, d3 = 0.f;
#pragma unroll
            for (int d = 0; d < HD_; d += 4) {
                float4 kv = *reinterpret_cast<const float4*>(&kr[d]);
                d0 = fmaf(sq[d + 0], kv.x, d0);
                d1 = fmaf(sq[d + 1], kv.y, d1);
                d2 = fmaf(sq[d + 2], kv.z, d2);
                d3 = fmaf(sq[d + 3], kv.w, d3);
            }
            s = (d0 + d1 + d2 + d3) * 0.125f;   // 1/sqrt(64)
        }
        sc[j] = s;
        lmax = fmaxf(lmax, s);
    }

    // block max reduce
#pragma unroll
    for (int o = 16; o > 0; o >>= 1)
        lmax = fmaxf(lmax, __shfl_xor_sync(0xffffffffu, lmax, o));
    if ((tid & 31) == 0) red[tid >> 5] = lmax;
    __syncthreads();
    float mx = fmaxf(fmaxf(red[0], red[1]), fmaxf(red[2], red[3]));
    __syncthreads();

    // exp + sum
    float lsum = 0.f;
    for (int j = tid; j < N_; j += 128) {
        float p = __expf(sc[j] - mx);
        sc[j] = p;
        lsum += p;
    }
#pragma unroll
    for (int o = 16; o > 0; o >>= 1)
        lsum += __shfl_xor_sync(0xffffffffu, lsum, o);
    if ((tid & 31) == 0) red[tid >> 5] = lsum;
    __syncthreads();
    float inv = 1.0f / (red[0] + red[1] + red[2] + red[3]);

    // weighted sum over V: 2 j-partitions x 64 dims
    int d    = tid & 63;
    int half = tid >> 6;
    const float* vb = v + (size_t)b * N_ * D_ + h * HD_ + d;
    float acc = 0.f;
    for (int j = half; j < N_; j += 2)
        acc = fmaf(sc[j], vb[(size_t)j * D_], acc);

    if (half) sacc[d] = acc;
    __syncthreads();
    if (!half)
        out[((size_t)(b * N_ + n)) * D_ + h * HD_ + d] = (acc + sacc[d]) * inv;
}

// ---------------------------------------------------------------------------
// Fused bias + residual + LayerNorm: one CTA (128 threads) per row of 512.
// ---------------------------------------------------------------------------
__global__ __launch_bounds__(128) void ln_kernel(
    const float* __restrict__ proj, const float* __restrict__ x,
    const float* __restrict__ bo, const float* __restrict__ gamma,
    const float* __restrict__ beta, float* __restrict__ out)
{
    int row = blockIdx.x;
    int tid = threadIdx.x;
    size_t base = (size_t)row * D_ + tid * 4;

    float4 p  = *reinterpret_cast<const float4*>(&proj[base]);
    float4 xv = *reinterpret_cast<const float4*>(&x[base]);
    float4 bv = *reinterpret_cast<const float4*>(&bo[tid * 4]);

    float y0 = p.x + bv.x + xv.x;
    float y1 = p.y + bv.y + xv.y;
    float y2 = p.z + bv.z + xv.z;
    float y3 = p.w + bv.w + xv.w;

    float s  = y0 + y1 + y2 + y3;
    float sq = y0 * y0 + y1 * y1 + y2 * y2 + y3 * y3;

    __shared__ float reds[4], redq[4];
#pragma unroll
    for (int o = 16; o > 0; o >>= 1) {
        s  += __shfl_xor_sync(0xffffffffu, s, o);
        sq += __shfl_xor_sync(0xffffffffu, sq, o);
    }
    if ((tid & 31) == 0) { reds[tid >> 5] = s; redq[tid >> 5] = sq; }
    __syncthreads();
    float tot  = reds[0] + reds[1] + reds[2] + reds[3];
    float totq = redq[0] + redq[1] + redq[2] + redq[3];

    float mu  = tot * (1.0f / D_);
    float var = totq * (1.0f / D_) - mu * mu;
    float rstd = rsqrtf(var + 1e-5f);

    float4 gv = *reinterpret_cast<const float4*>(&gamma[tid * 4]);
    float4 be = *reinterpret_cast<const float4*>(&beta[tid * 4]);

    float4 o4;
    o4.x = (y0 - mu) * rstd * gv.x + be.x;
    o4.y = (y1 - mu) * rstd * gv.y + be.y;
    o4.z = (y2 - mu) * rstd * gv.z + be.z;
    o4.w = (y3 - mu) * rstd * gv.w + be.w;
    *reinterpret_cast<float4*>(&out[base]) = o4;
}

// ---------------------------------------------------------------------------
extern "C" void kernel_launch(void* const* d_in, const int* in_sizes, int n_in,
                              void* d_out, int out_size)
{
    const float* x     = (const float*)d_in[0];
    const int*   adj   = (const int*)  d_in[1];
    const float* wq    = (const float*)d_in[2];
    const float* wk    = (const float*)d_in[3];
    const float* wv    = (const float*)d_in[4];
    const float* wo    = (const float*)d_in[5];
    const float* bo    = (const float*)d_in[6];
    const float* gamma = (const float*)d_in[7];
    const float* beta  = (const float*)d_in[8];
    float* out = (float*)d_out;

    float *q, *k, *v, *ao, *pr;
    cudaGetSymbolAddress((void**)&q,  g_q);
    cudaGetSymbolAddress((void**)&k,  g_k);
    cudaGetSymbolAddress((void**)&v,  g_v);
    cudaGetSymbolAddress((void**)&ao, g_ao);
    cudaGetSymbolAddress((void**)&pr, g_pr);

    dim3 gemm_grid(D_ / 64, M_ / 64);   // (8, 128)
    sgemm_nt_kernel<<<gemm_grid, 256>>>(x, wq, q, M_, D_, D_);
    sgemm_nt_kernel<<<gemm_grid, 256>>>(x, wk, k, M_, D_, D_);
    sgemm_nt_kernel<<<gemm_grid, 256>>>(x, wv, v, M_, D_, D_);

    attn_kernel<<<dim3(N_, H_, B_), 128>>>(q, k, v, adj, ao);

    sgemm_nt_kernel<<<gemm_grid, 256>>>(ao, wo, pr, M_, D_, D_);

    ln_kernel<<<M_, 128>>>(pr, x, bo, gamma, beta, out);
}

// round 4
// speedup vs baseline: 2.4430x; 2.4430x over previous
#include <cuda_runtime.h>
#include <math.h>

#define B_ 8
#define N_ 1024
#define D_ 512
#define H_ 8
#define HD_ 64
#define M_ (B_ * N_)   // 8192 rows
#define TQ 32
#define TK 128

// Scratch (device globals: allocation-free per harness rules)
__device__ float g_q[M_ * D_];
__device__ float g_k[M_ * D_];
__device__ float g_v[M_ * D_];
__device__ float g_ao[M_ * D_];
__device__ float g_pr[M_ * D_];

// ---------------------------------------------------------------------------
// SGEMM: C[M,Nc] = A[M,K] @ W[Nc,K]^T. 128x128 tile, BK=8, 256 thr, 8x8 micro,
// double-buffered smem (single sync per k-tile).
// ---------------------------------------------------------------------------
__global__ __launch_bounds__(256) void sgemm128(
    const float* __restrict__ A, const float* __restrict__ W,
    float* __restrict__ C, int M, int Nc, int K)
{
    __shared__ float As[2][8][128];
    __shared__ float Ws[2][8][128];

    const int t  = threadIdx.x;
    const int m0 = blockIdx.y * 128;
    const int n0 = blockIdx.x * 128;

    const int lr = t >> 1;          // 0..127
    const int lk = (t & 1) * 4;     // 0 or 4

    const float* Ap = A + (size_t)(m0 + lr) * K + lk;
    const float* Wp = W + (size_t)(n0 + lr) * K + lk;

    const int tx = t & 15;          // col group (n)
    const int ty = t >> 4;          // row group (m)

    float acc[8][8];
#pragma unroll
    for (int i = 0; i < 8; i++)
#pragma unroll
        for (int j = 0; j < 8; j++) acc[i][j] = 0.0f;

    // preload tile 0
    {
        float4 a = *reinterpret_cast<const float4*>(Ap);
        float4 w = *reinterpret_cast<const float4*>(Wp);
        As[0][lk + 0][lr] = a.x; As[0][lk + 1][lr] = a.y;
        As[0][lk + 2][lr] = a.z; As[0][lk + 3][lr] = a.w;
        Ws[0][lk + 0][lr] = w.x; Ws[0][lk + 1][lr] = w.y;
        Ws[0][lk + 2][lr] = w.z; Ws[0][lk + 3][lr] = w.w;
    }
    __syncthreads();

    const int nTiles = K >> 3;
    int buf = 0;
    for (int tile = 0; tile < nTiles; ++tile) {
        float4 an, wn;
        const bool more = (tile + 1 < nTiles);
        if (more) {
            an = *reinterpret_cast<const float4*>(Ap + (tile + 1) * 8);
            wn = *reinterpret_cast<const float4*>(Wp + (tile + 1) * 8);
        }
#pragma unroll
        for (int kk = 0; kk < 8; kk++) {
            float av[8], wv[8];
            *reinterpret_cast<float4*>(&av[0]) = *reinterpret_cast<const float4*>(&As[buf][kk][ty * 8]);
            *reinterpret_cast<float4*>(&av[4]) = *reinterpret_cast<const float4*>(&As[buf][kk][ty * 8 + 4]);
            *reinterpret_cast<float4*>(&wv[0]) = *reinterpret_cast<const float4*>(&Ws[buf][kk][tx * 8]);
            *reinterpret_cast<float4*>(&wv[4]) = *reinterpret_cast<const float4*>(&Ws[buf][kk][tx * 8 + 4]);
#pragma unroll
            for (int i = 0; i < 8; i++)
#pragma unroll
                for (int j = 0; j < 8; j++)
                    acc[i][j] = fmaf(av[i], wv[j], acc[i][j]);
        }
        if (more) {
            const int nb = buf ^ 1;
            As[nb][lk + 0][lr] = an.x; As[nb][lk + 1][lr] = an.y;
            As[nb][lk + 2][lr] = an.z; As[nb][lk + 3][lr] = an.w;
            Ws[nb][lk + 0][lr] = wn.x; Ws[nb][lk + 1][lr] = wn.y;
            Ws[nb][lk + 2][lr] = wn.z; Ws[nb][lk + 3][lr] = wn.w;
            __syncthreads();
            buf = nb;
        }
    }

#pragma unroll
    for (int i = 0; i < 8; i++) {
        float* cp = &C[(size_t)(m0 + ty * 8 + i) * Nc + n0 + tx * 8];
        *reinterpret_cast<float4*>(cp)     = make_float4(acc[i][0], acc[i][1], acc[i][2], acc[i][3]);
        *reinterpret_cast<float4*>(cp + 4) = make_float4(acc[i][4], acc[i][5], acc[i][6], acc[i][7]);
    }
}

// ---------------------------------------------------------------------------
// Flash-style attention: CTA = (32 queries, one (b,h)); 256 threads.
// Loops 128-key tiles: S=Q@K^T (masked) -> online softmax -> O += P@V.
// ---------------------------------------------------------------------------
struct AttnSmem {
    float Qs[HD_][TQ];       // d-major Q tile
    float Ks[HD_][TK];       // d-major K tile
    float Vs[TK][68];        // row-major V tile (padded)
    float Ss[TQ][132];       // score tile (padded)
    float m[TQ], l[TQ], sc[TQ];
};

__global__ __launch_bounds__(256) void attn_flash(
    const float* __restrict__ q, const float* __restrict__ k,
    const float* __restrict__ v, const int* __restrict__ adj,
    float* __restrict__ out)
{
    extern __shared__ char smem_raw[];
    AttnSmem& S = *reinterpret_cast<AttnSmem*>(smem_raw);

    const int qt = blockIdx.x, h = blockIdx.y, b = blockIdx.z;
    const int t  = threadIdx.x;
    const int q0 = qt * TQ;
    const size_t browbase = (size_t)b * N_;

    // load Q tile (d-major)
    {
        const int qr = t >> 3;              // 0..31
        const int d0 = (t & 7) * 8;         // 0..56
        const float* qp = q + (browbase + q0 + qr) * D_ + h * HD_ + d0;
        float4 x0 = *reinterpret_cast<const float4*>(qp);
        float4 x1 = *reinterpret_cast<const float4*>(qp + 4);
        S.Qs[d0 + 0][qr] = x0.x; S.Qs[d0 + 1][qr] = x0.y;
        S.Qs[d0 + 2][qr] = x0.z; S.Qs[d0 + 3][qr] = x0.w;
        S.Qs[d0 + 4][qr] = x1.x; S.Qs[d0 + 5][qr] = x1.y;
        S.Qs[d0 + 6][qr] = x1.z; S.Qs[d0 + 7][qr] = x1.w;
    }
    if (t < TQ) { S.m[t] = -1e30f; S.l[t] = 0.0f; }

    const int aq = (t >> 5) * 4;    // phase A: 4 query rows
    const int aj = (t & 31) * 4;    // phase A: 4 key cols
    const int bq = t >> 3;          // phase B: query
    const int bl = t & 7;           // phase B: lane in 8-group
    const int cq = (t >> 4) * 2;    // phase C: 2 query rows
    const int cd = (t & 15) * 4;    // phase C: 4 dims

    float oacc[2][4] = {{0.f,0.f,0.f,0.f},{0.f,0.f,0.f,0.f}};

    const int   lrow = t >> 1;              // 0..127 (K/V loads)
    const int   ldb  = (t & 1) * 32;        // 0 or 32
    const float* kbase = k + browbase * D_ + h * HD_;
    const float* vbase = v + browbase * D_ + h * HD_;

    __syncthreads();

    for (int j0 = 0; j0 < N_; j0 += TK) {
        // ---- load K (d-major) and V (row-major) tiles ----
        {
            const float* kp = kbase + (size_t)(j0 + lrow) * D_ + ldb;
            const float* vp = vbase + (size_t)(j0 + lrow) * D_ + ldb;
#pragma unroll
            for (int i = 0; i < 8; i++) {
                float4 kv = *reinterpret_cast<const float4*>(kp + i * 4);
                int d = ldb + i * 4;
                S.Ks[d + 0][lrow] = kv.x; S.Ks[d + 1][lrow] = kv.y;
                S.Ks[d + 2][lrow] = kv.z; S.Ks[d + 3][lrow] = kv.w;
                float4 vv = *reinterpret_cast<const float4*>(vp + i * 4);
                *reinterpret_cast<float4*>(&S.Vs[lrow][d]) = vv;
            }
        }
        __syncthreads();

        // ---- Phase A: S = scale*(Q@K^T) with adjacency mask ----
        {
            float sacc[4][4];
#pragma unroll
            for (int i = 0; i < 4; i++)
#pragma unroll
                for (int j = 0; j < 4; j++) sacc[i][j] = 0.0f;

#pragma unroll 8
            for (int d = 0; d < HD_; d++) {
                float4 qv = *reinterpret_cast<const float4*>(&S.Qs[d][aq]);
                float4 kv = *reinterpret_cast<const float4*>(&S.Ks[d][aj]);
                const float qa[4] = {qv.x, qv.y, qv.z, qv.w};
                const float ka[4] = {kv.x, kv.y, kv.z, kv.w};
#pragma unroll
                for (int i = 0; i < 4; i++)
#pragma unroll
                    for (int j = 0; j < 4; j++)
                        sacc[i][j] = fmaf(qa[i], ka[j], sacc[i][j]);
            }
#pragma unroll
            for (int i = 0; i < 4; i++) {
                const int* ap = adj + (browbase + q0 + aq + i) * N_ + j0 + aj;
                int4 a4 = *reinterpret_cast<const int4*>(ap);
                float4 sv;
                sv.x = (a4.x > 0) ? sacc[i][0] * 0.125f : -10000.0f;
                sv.y = (a4.y > 0) ? sacc[i][1] * 0.125f : -10000.0f;
                sv.z = (a4.z > 0) ? sacc[i][2] * 0.125f : -10000.0f;
                sv.w = (a4.w > 0) ? sacc[i][3] * 0.125f : -10000.0f;
                *reinterpret_cast<float4*>(&S.Ss[aq + i][aj]) = sv;
            }
        }
        __syncthreads();

        // ---- Phase B: online softmax update (8 threads per query) ----
        {
            float scv[16];
#pragma unroll
            for (int i = 0; i < 4; i++)
                *reinterpret_cast<float4*>(&scv[i * 4]) =
                    *reinterpret_cast<const float4*>(&S.Ss[bq][bl * 16 + i * 4]);
            float mx = scv[0];
#pragma unroll
            for (int i = 1; i < 16; i++) mx = fmaxf(mx, scv[i]);
#pragma unroll
            for (int o = 4; o > 0; o >>= 1)
                mx = fmaxf(mx, __shfl_xor_sync(0xffffffffu, mx, o));
            const float mold = S.m[bq];
            const float mnew = fmaxf(mold, mx);
            float sum = 0.0f;
#pragma unroll
            for (int i = 0; i < 16; i++) {
                scv[i] = __expf(scv[i] - mnew);
                sum += scv[i];
            }
#pragma unroll
            for (int i = 0; i < 4; i++)
                *reinterpret_cast<float4*>(&S.Ss[bq][bl * 16 + i * 4]) =
                    *reinterpret_cast<const float4*>(&scv[i * 4]);
#pragma unroll
            for (int o = 4; o > 0; o >>= 1)
                sum += __shfl_xor_sync(0xffffffffu, sum, o);
            if (bl == 0) {
                const float scl = __expf(mold - mnew);
                S.m[bq]  = mnew;
                S.sc[bq] = scl;
                S.l[bq]  = S.l[bq] * scl + sum;
            }
        }
        __syncthreads();

        // ---- Phase C: O = O*scale + P@V ----
        {
            const float s0 = S.sc[cq], s1 = S.sc[cq + 1];
#pragma unroll
            for (int j = 0; j < 4; j++) { oacc[0][j] *= s0; oacc[1][j] *= s1; }
#pragma unroll 8
            for (int j = 0; j < TK; j++) {
                const float p0 = S.Ss[cq][j];
                const float p1 = S.Ss[cq + 1][j];
                float4 vv = *reinterpret_cast<const float4*>(&S.Vs[j][cd]);
                oacc[0][0] = fmaf(p0, vv.x, oacc[0][0]);
                oacc[0][1] = fmaf(p0, vv.y, oacc[0][1]);
                oacc[0][2] = fmaf(p0, vv.z, oacc[0][2]);
                oacc[0][3] = fmaf(p0, vv.w, oacc[0][3]);
                oacc[1][0] = fmaf(p1, vv.x, oacc[1][0]);
                oacc[1][1] = fmaf(p1, vv.y, oacc[1][1]);
                oacc[1][2] = fmaf(p1, vv.z, oacc[1][2]);
                oacc[1][3] = fmaf(p1, vv.w, oacc[1][3]);
            }
        }
        __syncthreads();
    }

    // epilogue
    {
        const float inv0 = 1.0f / S.l[cq];
        const float inv1 = 1.0f / S.l[cq + 1];
        float* op0 = out + (browbase + q0 + cq) * D_ + h * HD_ + cd;
        float* op1 = op0 + D_;
        *reinterpret_cast<float4*>(op0) =
            make_float4(oacc[0][0] * inv0, oacc[0][1] * inv0, oacc[0][2] * inv0, oacc[0][3] * inv0);
        *reinterpret_cast<float4*>(op1) =
            make_float4(oacc[1][0] * inv1, oacc[1][1] * inv1, oacc[1][2] * inv1, oacc[1][3] * inv1);
    }
}

// ---------------------------------------------------------------------------
// Fused bias + residual + LayerNorm: one CTA (128 threads) per row of 512.
// ---------------------------------------------------------------------------
__global__ __launch_bounds__(128) void ln_kernel(
    const float* __restrict__ proj, const float* __restrict__ x,
    const float* __restrict__ bo, const float* __restrict__ gamma,
    const float* __restrict__ beta, float* __restrict__ out)
{
    int row = blockIdx.x;
    int tid = threadIdx.x;
    size_t base = (size_t)row * D_ + tid * 4;

    float4 p  = *reinterpret_cast<const float4*>(&proj[base]);
    float4 xv = *reinterpret_cast<const float4*>(&x[base]);
    float4 bv = *reinterpret_cast<const float4*>(&bo[tid * 4]);

    float y0 = p.x + bv.x + xv.x;
    float y1 = p.y + bv.y + xv.y;
    float y2 = p.z + bv.z + xv.z;
    float y3 = p.w + bv.w + xv.w;

    float s  = y0 + y1 + y2 + y3;
    float sq = y0 * y0 + y1 * y1 + y2 * y2 + y3 * y3;

    __shared__ float reds[4], redq[4];
#pragma unroll
    for (int o = 16; o > 0; o >>= 1) {
        s  += __shfl_xor_sync(0xffffffffu, s, o);
        sq += __shfl_xor_sync(0xffffffffu, sq, o);
    }
    if ((tid & 31) == 0) { reds[tid >> 5] = s; redq[tid >> 5] = sq; }
    __syncthreads();
    float tot  = reds[0] + reds[1] + reds[2] + reds[3];
    float totq = redq[0] + redq[1] + redq[2] + redq[3];

    float mu  = tot * (1.0f / D_);
    float var = totq * (1.0f / D_) - mu * mu;
    float rstd = rsqrtf(var + 1e-5f);

    float4 gv = *reinterpret_cast<const float4*>(&gamma[tid * 4]);
    float4 be = *reinterpret_cast<const float4*>(&beta[tid * 4]);

    float4 o4;
    o4.x = (y0 - mu) * rstd * gv.x + be.x;
    o4.y = (y1 - mu) * rstd * gv.y + be.y;
    o4.z = (y2 - mu) * rstd * gv.z + be.z;
    o4.w = (y3 - mu) * rstd * gv.w + be.w;
    *reinterpret_cast<float4*>(&out[base]) = o4;
}

// ---------------------------------------------------------------------------
extern "C" void kernel_launch(void* const* d_in, const int* in_sizes, int n_in,
                              void* d_out, int out_size)
{
    const float* x     = (const float*)d_in[0];
    const int*   adj   = (const int*)  d_in[1];
    const float* wq    = (const float*)d_in[2];
    const float* wk    = (const float*)d_in[3];
    const float* wv    = (const float*)d_in[4];
    const float* wo    = (const float*)d_in[5];
    const float* bo    = (const float*)d_in[6];
    const float* gamma = (const float*)d_in[7];
    const float* beta  = (const float*)d_in[8];
    float* out = (float*)d_out;

    float *q, *k, *v, *ao, *pr;
    cudaGetSymbolAddress((void**)&q,  g_q);
    cudaGetSymbolAddress((void**)&k,  g_k);
    cudaGetSymbolAddress((void**)&v,  g_v);
    cudaGetSymbolAddress((void**)&ao, g_ao);
    cudaGetSymbolAddress((void**)&pr, g_pr);

    static bool attr_set = false;
    if (!attr_set) {
        cudaFuncSetAttribute(attn_flash, cudaFuncAttributeMaxDynamicSharedMemorySize,
                             (int)sizeof(AttnSmem));
        attr_set = true;
    }

    dim3 gemm_grid(D_ / 128, M_ / 128);   // (4, 64)
    sgemm128<<<gemm_grid, 256>>>(x, wq, q, M_, D_, D_);
    sgemm128<<<gemm_grid, 256>>>(x, wk, k, M_, D_, D_);
    sgemm128<<<gemm_grid, 256>>>(x, wv, v, M_, D_, D_);

    attn_flash<<<dim3(N_ / TQ, H_, B_), 256, sizeof(AttnSmem)>>>(q, k, v, adj, ao);

    sgemm128<<<gemm_grid, 256>>>(ao, wo, pr, M_, D_, D_);

    ln_kernel<<<M_, 128>>>(pr, x, bo, gamma, beta, out);
}